// round 14
// baseline (speedup 1.0000x reference)
#include <cuda_runtime.h>
#include <cuda_bf16.h>
#include <cstdint>
#include <math.h>

#define S      512
#define BATCH  64
#define TLEN   1024
#define OBS_N  32000
#define NTHREADS 256
#define JH     256              // j-columns per CTA (cluster of 2)
#define LOG2E 1.4426950408889634f
#define LN2   0.6931471805599453f
#define L2Q   15.988707f        // log2(255*255)

// ---------------- device scratch ---------------------------------------------
__device__ float g_lseRow[S];
__device__ float g_mT[S];
__device__ float g_lseObs[S];
// quantized expT, per-rank copy with CTA-local i-chunk order:
// addr = rank*131072 + c*4096 + j_local*16 + b
//   c<16 : global i = rank*256     + 16*c      + b   (own half)
//   c>=16: global i = (1-rank)*256 + 16*(c-16) + b   (peer half)
__device__ unsigned char g_expTq[2 * 32 * 4096];

// ---------------- helpers -----------------------------------------------------
__device__ __forceinline__ float ex2_fast(float x) {   // MUFU.EX2
    float r;
    asm("ex2.approx.ftz.f32 %0, %1;" : "=f"(r) : "f"(x));
    return r;
}
__device__ __forceinline__ unsigned redux_max_u32(unsigned v) {
    unsigned r;
    asm("redux.sync.max.u32 %0, %1, 0xffffffff;" : "=r"(r) : "r"(v));
    return r;
}
__device__ __forceinline__ uint32_t smem_u32(const void* p) {
    uint32_t a;
    asm("{ .reg .u64 t; cvta.to.shared.u64 t, %1; cvt.u32.u64 %0, t; }"
        : "=r"(a) : "l"(p));
    return a;
}
__device__ __forceinline__ uint32_t mapa_u32(uint32_t a, uint32_t rank) {
    uint32_t d;
    asm("mapa.shared::cluster.u32 %0, %1, %2;" : "=r"(d) : "r"(a), "r"(rank));
    return d;
}
__device__ __forceinline__ void st_cluster_u8(uint32_t a, unsigned v) {
    asm volatile("st.shared::cluster.u8 [%0], %1;" :: "r"(a), "r"(v) : "memory");
}
__device__ __forceinline__ void st_cluster_u32(uint32_t a, unsigned v) {
    asm volatile("st.shared::cluster.u32 [%0], %1;" :: "r"(a), "r"(v) : "memory");
}
__device__ __forceinline__ void mbar_init(uint32_t a, unsigned cnt) {
    asm volatile("mbarrier.init.shared.b64 [%0], %1;" :: "r"(a), "r"(cnt) : "memory");
}
__device__ __forceinline__ void mbar_arrive_cluster(uint32_t a) {
    asm volatile("mbarrier.arrive.release.cluster.shared::cluster.b64 _, [%0];"
                 :: "r"(a) : "memory");
}
__device__ __forceinline__ void mbar_wait_cluster(uint32_t a, unsigned parity) {
    unsigned done;
    asm volatile(
        "{\n\t.reg .pred p;\n\t"
        "mbarrier.try_wait.parity.acquire.cluster.shared::cta.b64 p, [%1], %2;\n\t"
        "selp.b32 %0, 1, 0, p;\n\t}"
        : "=r"(done) : "r"(a), "r"(parity) : "memory");
    if (!done) {
        asm volatile(
            "{\n\t.reg .pred P1;\n\t"
            "WAIT_LOOP_%=:\n\t"
            "mbarrier.try_wait.parity.acquire.cluster.shared::cta.b64 P1, [%0], %1, 0x989680;\n\t"
            "@P1 bra.uni WAIT_DONE_%=;\n\t"
            "bra.uni WAIT_LOOP_%=;\n\t"
            "WAIT_DONE_%=:\n\t}"
            :: "r"(a), "r"(parity) : "memory");
    }
}
#define CLUSTER_SYNC() do { \
    asm volatile("barrier.cluster.arrive.aligned;" ::: "memory"); \
    asm volatile("barrier.cluster.wait.aligned;"   ::: "memory"); \
} while (0)

template <int NW>
__device__ __forceinline__ float blkMax(float v, float* red) {
    #pragma unroll
    for (int o = 16; o > 0; o >>= 1) v = fmaxf(v, __shfl_xor_sync(0xffffffffu, v, o));
    int w = threadIdx.x >> 5;
    if ((threadIdx.x & 31) == 0) red[w] = v;
    __syncthreads();
    float m = red[0];
    #pragma unroll
    for (int k = 1; k < NW; ++k) m = fmaxf(m, red[k]);
    __syncthreads();
    return m;
}
template <int NW>
__device__ __forceinline__ float blkSum(float v, float* red) {
    #pragma unroll
    for (int o = 16; o > 0; o >>= 1) v += __shfl_xor_sync(0xffffffffu, v, o);
    int w = threadIdx.x >> 5;
    if ((threadIdx.x & 31) == 0) red[w] = v;
    __syncthreads();
    float m = 0.f;
    #pragma unroll
    for (int k = 0; k < NW; ++k) m += red[k];
    __syncthreads();
    return m;
}

// ---------------- precompute (3 launches; k_forward = my launch #4) ------------
__global__ void k_rowlse(const float* __restrict__ ST) {
    __shared__ float red[8];
    int i = blockIdx.x, t = threadIdx.x;
    float x0 = ST[i * S + t], x1 = ST[i * S + t + 256];
    float M = blkMax<8>(fmaxf(x0, x1), red);
    float Ssum = blkSum<8>(expf(x0 - M) + expf(x1 - M), red);
    if (t == 0) g_lseRow[i] = M + logf(Ssum);
}
__global__ void k_colmax(const float* __restrict__ ST) {
    int j = blockIdx.x * blockDim.x + threadIdx.x;
    float m = -1e30f;
    for (int i = 0; i < S; ++i) m = fmaxf(m, ST[i * S + j] - g_lseRow[i]);
    g_mT[j] = m;
}
__global__ void k_pre3(const float* __restrict__ ST, const float* __restrict__ OT) {
    __shared__ float red[8];
    int i = blockIdx.x, t = threadIdx.x;
    float l = g_lseRow[i];
    for (int j = t; j < S; j += 256) {
        float e = expf(ST[i * S + j] - l - g_mT[j]);
        unsigned q = __float2uint_rn(fminf(e, 1.f) * 255.f);
        int r = j >> 8, jl = j & 255;
        int ihalf = i >> 8, il = i & 255;
        int c = ((ihalf == r) ? 0 : 16) + (il >> 4);
        int b = il & 15;
        g_expTq[r * 131072 + c * 4096 + jl * 16 + b] = (unsigned char)q;
    }
    const float* row = OT + (size_t)i * OBS_N;
    float m = -1e30f;
    for (int k = t; k < OBS_N; k += 256) m = fmaxf(m, row[k]);
    float M = blkMax<8>(m, red);
    float acc = 0.f;
    for (int k = t; k < OBS_N; k += 256) acc += expf(row[k] - M);
    float Ssum = blkSum<8>(acc, red);
    if (t == 0) g_lseObs[i] = M + logf(Ssum);
}

// ---------------- per-chain step (int8/dp4a matvec + quantized exchange) ------
__device__ __forceinline__ void hmm_step(
    int t, int wid, int step, int slot, float w, float cf,
    const unsigned char* __restrict__ sTq,
    unsigned char* sAqD, unsigned* sEoD, unsigned char* sRecvQ,
    uint32_t rqPeer, uint32_t mbLoc, uint32_t mbPeer,
    float& E2, float& rawOwn, int& ph0, int& ph1)
{
    // ---- wait exchange(step-1); acquire covers sRecvQ ----
    mbar_wait_cluster(mbLoc + slot * 8, (unsigned)(slot ? ph1 : ph0));
    if (slot) ph1 ^= 1; else ph0 ^= 1;
    const int rbuf = (step - 1) & 1;

    // ---- matvec: 32 dp4a chunks, 16 per-warp-group accumulators ----
    unsigned acc[16];
    #pragma unroll
    for (int g = 0; g < 16; ++g) acc[g] = 0u;
    {
        const uint4* aOwn = reinterpret_cast<const uint4*>(sAqD + rbuf * 256);
        const uint4* aPr  = reinterpret_cast<const uint4*>(sRecvQ + slot * 288);
        const uint4* ePtr = reinterpret_cast<const uint4*>(sTq + t * 16);
        #pragma unroll
        for (int c = 0; c < 16; ++c) {
            uint4 av = aOwn[c];
            uint4 ev = ePtr[c * 256];
            unsigned a = acc[c >> 1];
            a = __dp4a(av.x, ev.x, a);
            a = __dp4a(av.y, ev.y, a);
            a = __dp4a(av.z, ev.z, a);
            a = __dp4a(av.w, ev.w, a);
            acc[c >> 1] = a;
        }
        #pragma unroll
        for (int c = 0; c < 16; ++c) {
            uint4 av = aPr[c];
            uint4 ev = ePtr[(16 + c) * 256];
            unsigned a = acc[8 + (c >> 1)];
            a = __dp4a(av.x, ev.x, a);
            a = __dp4a(av.y, ev.y, a);
            a = __dp4a(av.z, ev.z, a);
            a = __dp4a(av.w, ev.w, a);
            acc[8 + (c >> 1)] = a;
        }
    }

    // ---- combine with 16 per-warp exponents ----
    unsigned be[16];
    {
        const unsigned* eo = sEoD + rbuf * 8;
        const unsigned* ep = reinterpret_cast<const unsigned*>(sRecvQ + slot * 288 + 256);
        #pragma unroll
        for (int g = 0; g < 8; ++g) { be[g] = eo[g]; be[8 + g] = ep[g]; }
    }
    unsigned bref = be[0];
    #pragma unroll
    for (int g = 1; g < 16; ++g) bref = max(bref, be[g]);
    float P = 0.f;
    #pragma unroll
    for (int g = 0; g < 16; ++g) {
        int d = (int)be[g] - (int)bref;
        d = (d < -126) ? -126 : d;
        P += (float)acc[g] * __uint_as_float((unsigned)(d + 127) << 23);
    }
    E2 += (float)((int)bref - 126);

    // ---- raw alpha(step), quantize, ship exchange(step) ----
    float raw = fmaxf(P * ex2_fast(fmaf(w + cf, LOG2E, -L2Q)), 1e-35f);
    unsigned bexp = __float_as_uint(raw) >> 23;
    unsigned bw = redux_max_u32(bexp);
    float qsf = __uint_as_float((253u - bw) << 23) * 255.f;
    unsigned q = __float2uint_rn(raw * qsf);

    const int sendSlot = slot ^ 1;
    const int wbuf = step & 1;
    sAqD[wbuf * 256 + t] = (unsigned char)q;
    st_cluster_u8(rqPeer + (unsigned)(sendSlot * 288 + t), q);
    if ((t & 31) == 0) {
        sEoD[wbuf * 8 + wid] = bw;
        st_cluster_u32(rqPeer + (unsigned)(sendSlot * 288 + 256 + wid * 4), bw);
    }
    mbar_arrive_cluster(mbPeer + sendSlot * 8);
    rawOwn = raw;
}

// ---------------- forward kernel ------------------------------------------------
// 256 threads, cluster of 2 (j-split). Each cluster runs TWO independent
// batches interleaved — chain 1's matvec hides chain 0's exchange latency
// and vice versa. One __syncthreads per step-pair.
//
// SMEM (bytes):
//  [0,131072)        sTq    u8 [32 c][256 j][16 b]      (shared by both chains)
//  [131072,132096)   sAqD   u8 [2 ch][2 buf][256]
//  [132096,132224)   sEoD   u32 [2 ch][2 buf][8]
//  [132224,133376)   sRecvQ [2 ch][2 slot][288]
//  [133376,141568)   sOb    int [2][1024]
//  [141568,141600)   sRed   f32 [8]
//  [141600,141632)   mbar   4 x u64  (2 per chain)
#define OFF_AQ   131072
#define OFF_EO   132096
#define OFF_RQ   132224
#define OFF_OB   133376
#define OFF_RED  141568
#define OFF_MB   141600
#define SMEM_TOTAL 141696

__global__ void __launch_bounds__(NTHREADS, 1) __cluster_dims__(2, 1, 1)
k_forward(const int* __restrict__ obs, const float* __restrict__ OT,
          const float* __restrict__ prior, float* __restrict__ out) {
    extern __shared__ char smem[];
    unsigned char* sTq   = reinterpret_cast<unsigned char*>(smem);
    unsigned char* sAqD  = reinterpret_cast<unsigned char*>(smem + OFF_AQ);
    unsigned*      sEoD  = reinterpret_cast<unsigned*>(smem + OFF_EO);
    unsigned char* sRecvQ= reinterpret_cast<unsigned char*>(smem + OFF_RQ);
    int*           sOb   = reinterpret_cast<int*>(smem + OFF_OB);
    float*         sRed  = reinterpret_cast<float*>(smem + OFF_RED);

    const int t    = threadIdx.x;
    const int rank = blockIdx.x & 1;
    const int b0   = (blockIdx.x >> 1) * 2;       // chains b0, b0+1
    const int wid  = t >> 5;

    const uint32_t mbLoc  = smem_u32(smem + OFF_MB);
    const uint32_t mbPeer = mapa_u32(mbLoc, (uint32_t)(rank ^ 1));
    const uint32_t rqLoc  = smem_u32(sRecvQ);
    const uint32_t rqPeer = mapa_u32(rqLoc, (uint32_t)(rank ^ 1));

    if (t == 0) {
        mbar_init(mbLoc,      NTHREADS); mbar_init(mbLoc + 8,  NTHREADS);
        mbar_init(mbLoc + 16, NTHREADS); mbar_init(mbLoc + 24, NTHREADS);
    }

    const int ownBase  = rank * JH;
    const int peerBase = (rank ^ 1) * JH;

    // one-time SMEM fill
    {
        const uint4* src = reinterpret_cast<const uint4*>(g_expTq + rank * 131072);
        uint4* dst = reinterpret_cast<uint4*>(sTq);
        for (int k = t; k < 131072 / 16; k += NTHREADS) dst[k] = src[k];
    }
    for (int k = t; k < 2 * TLEN; k += NTHREADS) sOb[k] = obs[b0 * TLEN + k];
    __syncthreads();

    // ---- init (both chains): prior lse once, alpha0 per chain ----
    float E2c[2], rawOwnc[2];
    float cf;
    {
        float p0 = prior[ownBase + t], p1 = prior[peerBase + t];
        float Mp = blkMax<8>(fmaxf(p0, p1), sRed);
        float Sp = blkSum<8>(expf(p0 - Mp) + expf(p1 - Mp), sRed);
        float lseP = Mp + logf(Sp);
        float lo0 = g_lseObs[ownBase + t];
        cf = g_mT[ownBase + t] - lo0;
        float addO = (p0 - lseP) - lo0;
        float addP = (p1 - lseP) - g_lseObs[peerBase + t];

        #pragma unroll
        for (int ch = 0; ch < 2; ++ch) {
            int o0 = sOb[ch * TLEN];
            float aO = __ldg(OT + (size_t)(ownBase + t) * OBS_N + o0) + addO;
            float aP = __ldg(OT + (size_t)(peerBase + t) * OBS_N + o0) + addP;
            float M = blkMax<8>(fmaxf(aO, aP), sRed);   // cluster-consistent ref
            E2c[ch] = M * LOG2E;
            float raw = fmaxf(ex2_fast((aO - M) * LOG2E), 1e-35f);
            rawOwnc[ch] = raw;
            unsigned bexp = __float_as_uint(raw) >> 23;
            unsigned bw = redux_max_u32(bexp);
            float qsf = __uint_as_float((253u - bw) << 23) * 255.f;
            unsigned q = __float2uint_rn(raw * qsf);
            sAqD[ch * 512 + t] = (unsigned char)q;      // buf 0
            st_cluster_u8(rqPeer + (unsigned)(ch * 576 + t), q);   // slot 0
            if ((t & 31) == 0) {
                sEoD[ch * 16 + wid] = bw;
                st_cluster_u32(rqPeer + (unsigned)(ch * 576 + 256 + wid * 4), bw);
            }
        }
    }
    CLUSTER_SYNC();                        // peer mbar inits + init stores visible
    mbar_arrive_cluster(mbPeer);           // chain 0, slot 0
    mbar_arrive_cluster(mbPeer + 16);      // chain 1, slot 0
    __syncthreads();

    const float* wPtr = OT + (size_t)(ownBase + t) * OBS_N;
    int slot = 0;
    int ph[4] = {0, 0, 0, 0};              // [chain][slot]

    #pragma unroll 1
    for (int step = 1; step <= TLEN; ++step) {
        const int ot0 = (step < TLEN) ? sOb[step] : 0;
        const int ot1 = (step < TLEN) ? sOb[TLEN + step] : 0;
        const float w0 = __ldg(wPtr + ot0);
        const float w1 = __ldg(wPtr + ot1);

        hmm_step(t, wid, step, slot, w0, cf, sTq,
                 sAqD,        sEoD,      sRecvQ,
                 rqPeer,       mbLoc,      mbPeer,
                 E2c[0], rawOwnc[0], ph[0], ph[1]);
        hmm_step(t, wid, step, slot, w1, cf, sTq,
                 sAqD + 512,  sEoD + 16, sRecvQ + 576,
                 rqPeer + 576, mbLoc + 16, mbPeer + 16,
                 E2c[1], rawOwnc[1], ph[2], ph[3]);

        __syncthreads();                   // bounds skew for sAqD/sEoD reuse
        slot ^= 1;
    }

    // ---- final per chain: own raw + dequantized peer raw ----
    #pragma unroll
    for (int ch = 0; ch < 2; ++ch) {
        mbar_wait_cluster(mbLoc + ch * 16 + slot * 8,
                          (unsigned)(ph[ch * 2 + slot]));
        unsigned qp = (unsigned)sRecvQ[ch * 576 + slot * 288 + t];
        unsigned beg = reinterpret_cast<const unsigned*>(
            sRecvQ + ch * 576 + slot * 288 + 256)[wid];
        float peerVal = (float)qp * __uint_as_float((beg + 1u) << 23) * (1.f / 255.f);
        float total = blkSum<8>(rawOwnc[ch] + peerVal, sRed);
        if (rank == 0 && t == 0) out[b0 + ch] = logf(total) + E2c[ch] * LN2;
    }
    CLUSTER_SYNC();
}

// ---------------- launch -------------------------------------------------------
extern "C" void kernel_launch(void* const* d_in, const int* in_sizes, int n_in,
                              void* d_out, int out_size) {
    const int*   obs   = (const int*)d_in[0];
    const float* ST    = (const float*)d_in[1];
    const float* OT    = (const float*)d_in[2];
    const float* prior = (const float*)d_in[3];
    float* out = (float*)d_out;

    cudaFuncSetAttribute(k_forward, cudaFuncAttributeMaxDynamicSharedMemorySize,
                         SMEM_TOTAL);

    k_rowlse<<<S, 256>>>(ST);
    k_colmax<<<4, 128>>>(ST);
    k_pre3<<<S, 256>>>(ST, OT);
    k_forward<<<BATCH, NTHREADS, SMEM_TOTAL>>>(obs, OT, prior, out);
}

// round 15
// speedup vs baseline: 1.5833x; 1.5833x over previous
#include <cuda_runtime.h>
#include <cuda_bf16.h>
#include <cstdint>
#include <math.h>

#define S      512
#define BATCH  64
#define TLEN   1024
#define OBS_N  32000
#define NTHREADS 512
#define JH     256              // j-columns per CTA (cluster of 2)
#define LOG2E 1.4426950408889634f
#define LN2   0.6931471805599453f
#define L2Q   15.988707f        // log2(255*255)

// ---------------- device scratch ---------------------------------------------
__device__ float g_lseRow[S];
__device__ float g_mT[S];
__device__ float g_lseObs[S];
// quantized expT, per-rank copy with CTA-local i-chunk order:
// addr = rank*131072 + c*4096 + j_local*16 + b
//   c<16 : global i = rank*256     + 16*c      + b   (own half)
//   c>=16: global i = (1-rank)*256 + 16*(c-16) + b   (peer half)
__device__ unsigned char g_expTq[2 * 32 * 4096];

// ---------------- helpers -----------------------------------------------------
__device__ __forceinline__ float ex2_fast(float x) {   // MUFU.EX2
    float r;
    asm("ex2.approx.ftz.f32 %0, %1;" : "=f"(r) : "f"(x));
    return r;
}
__device__ __forceinline__ unsigned redux_max_u32(unsigned v) {
    unsigned r;
    asm("redux.sync.max.u32 %0, %1, 0xffffffff;" : "=r"(r) : "r"(v));
    return r;
}
__device__ __forceinline__ uint32_t smem_u32(const void* p) {
    uint32_t a;
    asm("{ .reg .u64 t; cvta.to.shared.u64 t, %1; cvt.u32.u64 %0, t; }"
        : "=r"(a) : "l"(p));
    return a;
}
__device__ __forceinline__ uint32_t mapa_u32(uint32_t a, uint32_t rank) {
    uint32_t d;
    asm("mapa.shared::cluster.u32 %0, %1, %2;" : "=r"(d) : "r"(a), "r"(rank));
    return d;
}
__device__ __forceinline__ void st_cluster_u8(uint32_t a, unsigned v) {
    asm volatile("st.shared::cluster.u8 [%0], %1;" :: "r"(a), "r"(v) : "memory");
}
__device__ __forceinline__ void st_cluster_u32(uint32_t a, unsigned v) {
    asm volatile("st.shared::cluster.u32 [%0], %1;" :: "r"(a), "r"(v) : "memory");
}
__device__ __forceinline__ void mbar_init(uint32_t a, unsigned cnt) {
    asm volatile("mbarrier.init.shared.b64 [%0], %1;" :: "r"(a), "r"(cnt) : "memory");
}
__device__ __forceinline__ void mbar_arrive_cluster(uint32_t a) {
    asm volatile("mbarrier.arrive.release.cluster.shared::cluster.b64 _, [%0];"
                 :: "r"(a) : "memory");
}
__device__ __forceinline__ void mbar_wait_cluster(uint32_t a, unsigned parity) {
    unsigned done;
    asm volatile(
        "{\n\t.reg .pred p;\n\t"
        "mbarrier.try_wait.parity.acquire.cluster.shared::cta.b64 p, [%1], %2;\n\t"
        "selp.b32 %0, 1, 0, p;\n\t}"
        : "=r"(done) : "r"(a), "r"(parity) : "memory");
    if (!done) {
        asm volatile(
            "{\n\t.reg .pred P1;\n\t"
            "WAIT_LOOP_%=:\n\t"
            "mbarrier.try_wait.parity.acquire.cluster.shared::cta.b64 P1, [%0], %1, 0x989680;\n\t"
            "@P1 bra.uni WAIT_DONE_%=;\n\t"
            "bra.uni WAIT_LOOP_%=;\n\t"
            "WAIT_DONE_%=:\n\t}"
            :: "r"(a), "r"(parity) : "memory");
    }
}
#define CLUSTER_SYNC() do { \
    asm volatile("barrier.cluster.arrive.aligned;" ::: "memory"); \
    asm volatile("barrier.cluster.wait.aligned;"   ::: "memory"); \
} while (0)

template <int NW>
__device__ __forceinline__ float blkMax(float v, float* red) {
    #pragma unroll
    for (int o = 16; o > 0; o >>= 1) v = fmaxf(v, __shfl_xor_sync(0xffffffffu, v, o));
    int w = threadIdx.x >> 5;
    if ((threadIdx.x & 31) == 0) red[w] = v;
    __syncthreads();
    float m = red[0];
    #pragma unroll
    for (int k = 1; k < NW; ++k) m = fmaxf(m, red[k]);
    __syncthreads();
    return m;
}
template <int NW>
__device__ __forceinline__ float blkSum(float v, float* red) {
    #pragma unroll
    for (int o = 16; o > 0; o >>= 1) v += __shfl_xor_sync(0xffffffffu, v, o);
    int w = threadIdx.x >> 5;
    if ((threadIdx.x & 31) == 0) red[w] = v;
    __syncthreads();
    float m = 0.f;
    #pragma unroll
    for (int k = 0; k < NW; ++k) m += red[k];
    __syncthreads();
    return m;
}

// ---------------- precompute (3 launches; k_forward = my launch #4) ------------
__global__ void k_rowlse(const float* __restrict__ ST) {
    __shared__ float red[8];
    int i = blockIdx.x, t = threadIdx.x;
    float x0 = ST[i * S + t], x1 = ST[i * S + t + 256];
    float M = blkMax<8>(fmaxf(x0, x1), red);
    float Ssum = blkSum<8>(expf(x0 - M) + expf(x1 - M), red);
    if (t == 0) g_lseRow[i] = M + logf(Ssum);
}
__global__ void k_colmax(const float* __restrict__ ST) {
    int j = blockIdx.x * blockDim.x + threadIdx.x;
    float m = -1e30f;
    for (int i = 0; i < S; ++i) m = fmaxf(m, ST[i * S + j] - g_lseRow[i]);
    g_mT[j] = m;
}
__global__ void k_pre3(const float* __restrict__ ST, const float* __restrict__ OT) {
    __shared__ float red[8];
    int i = blockIdx.x, t = threadIdx.x;
    float l = g_lseRow[i];
    for (int j = t; j < S; j += 256) {
        float e = expf(ST[i * S + j] - l - g_mT[j]);
        unsigned q = __float2uint_rn(fminf(e, 1.f) * 255.f);
        int r = j >> 8, jl = j & 255;
        int ihalf = i >> 8, il = i & 255;
        int c = ((ihalf == r) ? 0 : 16) + (il >> 4);
        int b = il & 15;
        g_expTq[r * 131072 + c * 4096 + jl * 16 + b] = (unsigned char)q;
    }
    const float* row = OT + (size_t)i * OBS_N;
    float m = -1e30f;
    for (int k = t; k < OBS_N; k += 256) m = fmaxf(m, row[k]);
    float M = blkMax<8>(m, red);
    float acc = 0.f;
    for (int k = t; k < OBS_N; k += 256) acc += expf(row[k] - M);
    float Ssum = blkSum<8>(acc, red);
    if (t == 0) g_lseObs[i] = M + logf(Ssum);
}

// ---------------- forward kernel ------------------------------------------------
// 512 threads, cluster of 2 (j-split). Thread = (j, half):
//   j = wid*16 + (t&15),  half = (t>>4)&1
// half 0: chunks 0..15 (own-half i, own alpha bytes); half 1: chunks 16..31
// (peer-half i, bytes straight from recv slot). Halves combined by shfl_xor 16.
// Exponent groups: 16 j per warp -> 32 groups of 16 i, aligned with chunks.
// Per step: wait -> 16x(LDS e + dp4a) -> exp combine -> shfl -> ex2 -> redux ->
// quantize -> ship (half0 lanes) -> arrive -> one syncthreads.
//
// SMEM (bytes):
//  [0,131072)        sTq    u8 [32 c][256 j][16 b]
//  [131072,131584)   sAqD   u8 [2 buf][256]
//  [131584,131712)   sEoD   u32 [2 buf][16]
//  [131712,132352)   sRecvQ [2 slot][320]: u8 q[256] + u32 exps[16]
//  [132352,136448)   sOb    int [1024]
//  [136448,136512)   sRed   f32 [16]
//  [136512,136528)   mbar   2 x u64
#define OFF_AQ   131072
#define OFF_EO   131584
#define OFF_RQ   131712
#define OFF_OB   132352
#define OFF_RED  136448
#define OFF_MB   136512
#define SMEM_TOTAL 136576
#define RQ_STRIDE 320

__global__ void __launch_bounds__(NTHREADS, 1) __cluster_dims__(2, 1, 1)
k_forward(const int* __restrict__ obs, const float* __restrict__ OT,
          const float* __restrict__ prior, float* __restrict__ out) {
    extern __shared__ char smem[];
    unsigned char* sTq   = reinterpret_cast<unsigned char*>(smem);
    unsigned char* sAqD  = reinterpret_cast<unsigned char*>(smem + OFF_AQ);
    unsigned*      sEoD  = reinterpret_cast<unsigned*>(smem + OFF_EO);
    unsigned char* sRecvQ= reinterpret_cast<unsigned char*>(smem + OFF_RQ);
    int*           sOb   = reinterpret_cast<int*>(smem + OFF_OB);
    float*         sRed  = reinterpret_cast<float*>(smem + OFF_RED);

    const int t    = threadIdx.x;
    const int rank = blockIdx.x & 1;
    const int b    = blockIdx.x >> 1;
    const int wid  = t >> 5;
    const int j    = wid * 16 + (t & 15);       // output state (local)
    const int half = (t >> 4) & 1;              // i-half this thread covers

    const uint32_t mbLoc  = smem_u32(smem + OFF_MB);
    const uint32_t mbPeer = mapa_u32(mbLoc, (uint32_t)(rank ^ 1));
    const uint32_t rqPeer = mapa_u32(smem_u32(sRecvQ), (uint32_t)(rank ^ 1));

    if (t == 0) { mbar_init(mbLoc, NTHREADS); mbar_init(mbLoc + 8, NTHREADS); }

    const int ownBase  = rank * JH;
    const int peerBase = (rank ^ 1) * JH;

    // one-time SMEM fill
    {
        const uint4* src = reinterpret_cast<const uint4*>(g_expTq + rank * 131072);
        uint4* dst = reinterpret_cast<uint4*>(sTq);
        for (int k = t; k < 131072 / 16; k += NTHREADS) dst[k] = src[k];
    }
    for (int k = t; k < TLEN; k += NTHREADS) sOb[k] = obs[b * TLEN + k];
    __syncthreads();

    // ---- init: prior lse (block-wide), alpha0, ship exchange 0 ----
    float E2, rawOwn, cf;
    {
        float p0 = prior[ownBase + j], p1 = prior[peerBase + j];
        float Mp = blkMax<16>(fmaxf(p0, p1), sRed);
        float Sp = blkSum<16>(expf(p0 - Mp) + expf(p1 - Mp), sRed) * 0.5f; // dup halves
        float lseP = Mp + logf(Sp);
        float lo0 = g_lseObs[ownBase + j];
        cf = g_mT[ownBase + j] - lo0;

        int o0 = sOb[0];
        float aO = __ldg(OT + (size_t)(ownBase + j) * OBS_N + o0)
                   + (p0 - lseP) - lo0;
        float aP = __ldg(OT + (size_t)(peerBase + j) * OBS_N + o0)
                   + (p1 - lseP) - g_lseObs[peerBase + j];
        float M = blkMax<16>(fmaxf(aO, aP), sRed);   // cluster-consistent ref
        E2 = M * LOG2E;
        rawOwn = fmaxf(ex2_fast((aO - M) * LOG2E), 1e-35f);

        unsigned bexp = __float_as_uint(rawOwn) >> 23;
        unsigned bw = redux_max_u32(bexp);          // warp = 16 j (dup halves)
        float qsf = __uint_as_float((253u - bw) << 23) * 255.f;
        unsigned q = __float2uint_rn(rawOwn * qsf);
        if (half == 0) {
            sAqD[j] = (unsigned char)q;             // buf 0
            st_cluster_u8(rqPeer + (unsigned)j, q); // slot 0
        }
        if ((t & 31) == 0) {
            sEoD[wid] = bw;
            st_cluster_u32(rqPeer + 256u + (unsigned)wid * 4u, bw);
        }
    }
    CLUSTER_SYNC();                      // peer mbar inits + init stores visible
    mbar_arrive_cluster(mbPeer);         // exchange 0 on slot 0
    __syncthreads();

    const float* wPtr = OT + (size_t)(ownBase + j) * OBS_N;
    const uint4* ePtr = reinterpret_cast<const uint4*>(
        sTq + (size_t)(half * 16) * 4096 + j * 16);
    int slot = 0;
    int ph0 = 0, ph1 = 0;

    #pragma unroll 1
    for (int step = 1; step <= TLEN; ++step) {
        const int ot = (step < TLEN) ? sOb[step] : 0;
        const float w = __ldg(wPtr + ot);          // hidden under wait+matvec

        // ---- wait exchange(step-1); acquire covers sRecvQ ----
        mbar_wait_cluster(mbLoc + slot * 8, (unsigned)(slot ? ph1 : ph0));
        if (slot) ph1 ^= 1; else ph0 ^= 1;
        const int rbuf = (step - 1) & 1;

        // ---- matvec: 16 dp4a chunks (this thread's half of i) ----
        const uint4* aSrc = half
            ? reinterpret_cast<const uint4*>(sRecvQ + slot * RQ_STRIDE)
            : reinterpret_cast<const uint4*>(sAqD + rbuf * 256);
        unsigned acc[16];
        #pragma unroll
        for (int cc = 0; cc < 16; ++cc) {
            uint4 av = aSrc[cc];
            uint4 ev = ePtr[cc * 256];
            unsigned a = 0u;
            a = __dp4a(av.x, ev.x, a);
            a = __dp4a(av.y, ev.y, a);
            a = __dp4a(av.z, ev.z, a);
            a = __dp4a(av.w, ev.w, a);
            acc[cc] = a;
        }

        // ---- per-chunk exponents (16 groups of 16 i, aligned with chunks) ----
        const uint4* eSrc = half
            ? reinterpret_cast<const uint4*>(sRecvQ + slot * RQ_STRIDE + 256)
            : reinterpret_cast<const uint4*>(sEoD + rbuf * 16);
        unsigned be[16];
        #pragma unroll
        for (int g = 0; g < 4; ++g) {
            uint4 v = eSrc[g];
            be[g * 4] = v.x; be[g * 4 + 1] = v.y;
            be[g * 4 + 2] = v.z; be[g * 4 + 3] = v.w;
        }
        unsigned bl = be[0];
        #pragma unroll
        for (int g = 1; g < 16; ++g) bl = max(bl, be[g]);
        unsigned bref = max(bl, __shfl_xor_sync(0xffffffffu, bl, 16));
        float P = 0.f;
        #pragma unroll
        for (int g = 0; g < 16; ++g) {
            int d = (int)be[g] - (int)bref;
            d = (d < -126) ? -126 : d;
            P += (float)acc[g] * __uint_as_float((unsigned)(d + 127) << 23);
        }
        P += __shfl_xor_sync(0xffffffffu, P, 16);   // combine halves
        E2 += (float)((int)bref - 126);

        // ---- raw alpha(step), quantize, ship exchange(step) ----
        float raw = fmaxf(P * ex2_fast(fmaf(w + cf, LOG2E, -L2Q)), 1e-35f);
        unsigned bexp = __float_as_uint(raw) >> 23;
        unsigned bw = redux_max_u32(bexp);          // warp covers 16 j
        float qsf = __uint_as_float((253u - bw) << 23) * 255.f;
        unsigned q = __float2uint_rn(raw * qsf);

        const int sendSlot = slot ^ 1;
        const int wbuf = step & 1;
        if (half == 0) {
            sAqD[wbuf * 256 + j] = (unsigned char)q;
            st_cluster_u8(rqPeer + (unsigned)(sendSlot * RQ_STRIDE + j), q);
        }
        if ((t & 31) == 0) {
            sEoD[wbuf * 16 + wid] = bw;
            st_cluster_u32(rqPeer + (unsigned)(sendSlot * RQ_STRIDE + 256 + wid * 4), bw);
        }
        mbar_arrive_cluster(mbPeer + sendSlot * 8);
        rawOwn = raw;
        __syncthreads();                  // bounds skew for sAqD/sEoD reuse
        slot = sendSlot;
    }

    // ---- final: own raw + dequantized peer raw (exchange TLEN pending) ----
    mbar_wait_cluster(mbLoc + slot * 8, (unsigned)(slot ? ph1 : ph0));
    float v = 0.f;
    if (half == 0) {
        unsigned qp = (unsigned)sRecvQ[slot * RQ_STRIDE + j];
        unsigned beg = reinterpret_cast<const unsigned*>(
            sRecvQ + slot * RQ_STRIDE + 256)[j >> 4];
        float peerVal = (float)qp * __uint_as_float((beg + 1u) << 23) * (1.f / 255.f);
        v = rawOwn + peerVal;
    }
    float total = blkSum<16>(v, sRed);
    if (rank == 0 && t == 0) out[b] = logf(total) + E2 * LN2;
    CLUSTER_SYNC();
}

// ---------------- launch -------------------------------------------------------
extern "C" void kernel_launch(void* const* d_in, const int* in_sizes, int n_in,
                              void* d_out, int out_size) {
    const int*   obs   = (const int*)d_in[0];
    const float* ST    = (const float*)d_in[1];
    const float* OT    = (const float*)d_in[2];
    const float* prior = (const float*)d_in[3];
    float* out = (float*)d_out;

    cudaFuncSetAttribute(k_forward, cudaFuncAttributeMaxDynamicSharedMemorySize,
                         SMEM_TOTAL);

    k_rowlse<<<S, 256>>>(ST);
    k_colmax<<<4, 128>>>(ST);
    k_pre3<<<S, 256>>>(ST, OT);
    k_forward<<<BATCH * 2, NTHREADS, SMEM_TOTAL>>>(obs, OT, prior, out);
}